// round 4
// baseline (speedup 1.0000x reference)
#include <cuda_runtime.h>

#define NN  1024
#define RAW 128
#define DD  128
#define HH  256

#define SELU_ALPHA 1.6732632423543772f
#define SELU_SCALE 1.0507009873554805f

typedef unsigned long long ull;

// Packed f32x2 helpers (Blackwell sm_103a)
#define ADD2(d, a, b)    asm("add.rn.f32x2 %0, %1, %2;" : "=l"(d) : "l"(a), "l"(b))
#define FMA2(d, a, b, c) asm("fma.rn.f32x2 %0, %1, %2, %3;" : "=l"(d) : "l"(a), "l"(b), "l"(c))
#define PACK2(d, lo, hi) asm("mov.b64 %0, {%1, %2};" : "=l"(d) : "f"(lo), "f"(hi))
#define UNPACK2(lo, hi, s) asm("mov.b64 {%0, %1}, %2;" : "=f"(lo), "=f"(hi) : "l"(s))
#define MULSAT(d, a, b)  asm("mul.rn.sat.f32 %0, %1, %2;" : "=f"(d) : "f"(a), "f"(b))

// Scratch (static __device__ arrays; no allocation)
__device__ float  g_AT [HH * NN];   // A^T (incl. b1)          [k][j]
__device__ float  g_EAT[HH * NN];   // exp(A^T)                [k][j]
__device__ float  g_BT [HH * NN];   // B^T                     [k][i]
__device__ float  g_EBT[HH * NN];   // exp(B^T)                [k][i]
__device__ float  g_P  [NN];        // P[j] = sum_k (sw_k/2) A[k][j]
__device__ float  g_Q  [NN];        // Q[i] = sum_k (sw_k/2) B[k][i]
__device__ float2 g_hw2[HH];        // {sw/2, sw/2}
__device__ float2 g_aw2[HH];        // {asw, asw}
__device__ float  g_c0;             // b2 - sum asw
__device__ unsigned int g_tile;     // work-steal counter

// ---------------------------------------------------------------------------
// Fused aux kernel: prep (block 0) + z + A/B + exp + transposed stores + P/Q.
// 128 blocks x 256 threads; block handles j rows [j0, j0+8), thread t = k.
// ---------------------------------------------------------------------------
__global__ __launch_bounds__(256) void aux_kernel(
        const float* __restrict__ x,     const float* __restrict__ W_enc,
        const float* __restrict__ b_enc, const float* __restrict__ W1,
        const float* __restrict__ b1,    const float* __restrict__ W2,
        const float* __restrict__ b2) {
    __shared__ float sx[8][RAW];
    __shared__ float sz[8][DD];
    __shared__ float stV[HH * 9];
    __shared__ float stE[HH * 9];
    __shared__ float redR[8][8];

    const int t  = threadIdx.x;          // k in [0,256)
    const int j0 = blockIdx.x * 8;

    // ---- prep (block 0 only; uses stV as scratch, then barriers) ----
    if (blockIdx.x == 0) {
        float w   = W2[t];
        float sw  = SELU_SCALE * w;
        float asw = SELU_ALPHA * sw;
        g_hw2[t] = make_float2(0.5f * sw, 0.5f * sw);
        g_aw2[t] = make_float2(asw, asw);
        stV[t] = asw;
        __syncthreads();
        #pragma unroll
        for (int s = 128; s > 0; s >>= 1) {
            if (t < s) stV[t] += stV[t + s];
            __syncthreads();
        }
        if (t == 0) { g_c0 = b2[0] - stV[0]; g_tile = 0u; }
        __syncthreads();
    }

    // ---- load x rows into shared ----
    #pragma unroll
    for (int s = 0; s < 4; s++) {
        int idx = t + s * 256;
        sx[idx >> 7][idx & 127] = x[(j0 + (idx >> 7)) * RAW + (idx & 127)];
    }
    __syncthreads();

    // ---- z = x @ W_enc + b_enc (8 rows, in shared) ----
    {
        int k = t & 127, rh = t >> 7;
        float za[4] = {0.f, 0.f, 0.f, 0.f};
        for (int c = 0; c < RAW; c++) {
            float w = W_enc[c * DD + k];
            #pragma unroll
            for (int r = 0; r < 4; r++)
                za[r] = fmaf(sx[rh * 4 + r][c], w, za[r]);
        }
        float bb = b_enc[k];
        #pragma unroll
        for (int r = 0; r < 4; r++)
            sz[rh * 4 + r][k] = za[r] + bb;
    }
    __syncthreads();

    // ---- A = z@W1[:d]+b1, B = z@W1[d:] for the 8 rows ----
    float accA[8], accB[8];
    #pragma unroll
    for (int r = 0; r < 8; r++) { accA[r] = 0.f; accB[r] = 0.f; }
    for (int c = 0; c < DD; c++) {
        float wa = W1[c * HH + t];
        float wb = W1[(c + DD) * HH + t];
        #pragma unroll
        for (int r = 0; r < 8; r++) {
            float zz = sz[r][c];
            accA[r] = fmaf(zz, wa, accA[r]);
            accB[r] = fmaf(zz, wb, accB[r]);
        }
    }
    float b1k = b1[t];
    float hw  = 0.5f * SELU_SCALE * W2[t];

    const int wid = t >> 5, lid = t & 31;
    const int kx  = t >> 3, jt  = t & 7;

    // ---- round A: stores of AT/EAT (coalesced) + P reduction ----
    {
        float pv[8];
        #pragma unroll
        for (int r = 0; r < 8; r++) {
            float a = accA[r] + b1k;
            stV[t * 9 + r] = a;
            stE[t * 9 + r] = __expf(fminf(fmaxf(a, -60.f), 60.f));
            pv[r] = hw * a;
        }
        #pragma unroll
        for (int r = 0; r < 8; r++) {
            float v = pv[r];
            #pragma unroll
            for (int s = 16; s > 0; s >>= 1)
                v += __shfl_down_sync(0xffffffffu, v, s);
            if (lid == 0) redR[wid][r] = v;
        }
        __syncthreads();
        #pragma unroll
        for (int p = 0; p < 8; p++) {
            int k = p * 32 + kx;
            g_AT [k * NN + j0 + jt] = stV[k * 9 + jt];
            g_EAT[k * NN + j0 + jt] = stE[k * 9 + jt];
        }
        if (t < 8) {
            float s = 0.f;
            #pragma unroll
            for (int w2i = 0; w2i < 8; w2i++) s += redR[w2i][t];
            g_P[j0 + t] = s;
        }
        __syncthreads();
    }

    // ---- round B: stores of BT/EBT + Q reduction ----
    {
        float pv[8];
        #pragma unroll
        for (int r = 0; r < 8; r++) {
            float b = accB[r];
            stV[t * 9 + r] = b;
            stE[t * 9 + r] = __expf(fminf(fmaxf(b, -60.f), 60.f));
            pv[r] = hw * b;
        }
        #pragma unroll
        for (int r = 0; r < 8; r++) {
            float v = pv[r];
            #pragma unroll
            for (int s = 16; s > 0; s >>= 1)
                v += __shfl_down_sync(0xffffffffu, v, s);
            if (lid == 0) redR[wid][r] = v;
        }
        __syncthreads();
        #pragma unroll
        for (int p = 0; p < 8; p++) {
            int k = p * 32 + kx;
            g_BT [k * NN + j0 + jt] = stV[k * 9 + jt];
            g_EBT[k * NN + j0 + jt] = stE[k * 9 + jt];
        }
        if (t < 8) {
            float s = 0.f;
            #pragma unroll
            for (int w2i = 0; w2i < 8; w2i++) s += redR[w2i][t];
            g_Q[j0 + t] = s;
        }
    }
}

// ---------------------------------------------------------------------------
// Main: o[i,j] = hsig( P[j] + Q[i] + c0 + sum_k [ hw_k*|v| + asw_k*sat(e) ] )
//   v = A[k][j]+B[k][i], e = EA[k][j]*EB[k][i], hw = sw/2.
// Work-steal over 512 tiles of 64(j) x 32(i). 128 threads, 4x4 per thread.
// Packed f32x2: ADD2 for v, AND-abs, dup-packed weights, FFMA2 accumulate.
// ---------------------------------------------------------------------------
#define TJ 64
#define TI 32
#define NTILE ((NN / TJ) * (NN / TI))   // 512

__global__ __launch_bounds__(128, 4) void main_kernel(float* __restrict__ out) {
    __shared__ float4 s_a [16][16];
    __shared__ float4 s_ea[16][16];
    __shared__ float4 s_bd[16][16];   // {b,b} dup pairs, 2 f4 per 4 i's
    __shared__ float4 s_eb[16][8];
    __shared__ float2 s_w [16];
    __shared__ float2 s_aw[16];
    __shared__ unsigned int s_t;

    const int tid = threadIdx.x;
    const int tx  = tid & 15;   // j quad
    const int ty  = tid >> 4;   // i quad (0..7)

    const float4* AT4  = reinterpret_cast<const float4*>(g_AT);
    const float4* EAT4 = reinterpret_cast<const float4*>(g_EAT);
    const float4* BT4  = reinterpret_cast<const float4*>(g_BT);
    const float4* EBT4 = reinterpret_cast<const float4*>(g_EBT);

    const int ar = tid >> 4, ac = tid & 15;   // A loader coords
    const int br = tid >> 3, bc = tid & 7;    // B loader coords

    const float c0 = g_c0;

    for (;;) {
        __syncthreads();                       // protect s_t + shared reuse
        if (tid == 0) s_t = atomicAdd(&g_tile, 1u);
        __syncthreads();
        unsigned int tt = s_t;
        if (tt >= NTILE) break;
        const int j0 = (int)(tt & 15) * TJ;
        const int i0 = (int)(tt >> 4) * TI;

        ull acc[4][2];
        #pragma unroll
        for (int i = 0; i < 4; i++) { acc[i][0] = 0ull; acc[i][1] = 0ull; }

        // prefetch chunk 0
        float4 pa0, pa1, pea0, pea1, pb, peb;
        float2 pw = make_float2(0.f, 0.f), paw = make_float2(0.f, 0.f);
        {
            int ga = ar * (NN / 4) + (j0 >> 2) + ac;
            pa0  = AT4 [ga];            pea0 = EAT4[ga];
            pa1  = AT4 [ga + 8 * (NN / 4)];
            pea1 = EAT4[ga + 8 * (NN / 4)];
            int gb = br * (NN / 4) + (i0 >> 2) + bc;
            pb  = BT4 [gb];
            peb = EBT4[gb];
            if (tid < 16)      pw  = g_hw2[tid];
            else if (tid < 32) paw = g_aw2[tid - 16];
        }

        for (int c = 0; c < 16; c++) {
            __syncthreads();
            s_a [ar    ][ac] = pa0;
            s_a [ar + 8][ac] = pa1;
            s_ea[ar    ][ac] = pea0;
            s_ea[ar + 8][ac] = pea1;
            s_bd[br][bc * 2]     = make_float4(pb.x, pb.x, pb.y, pb.y);
            s_bd[br][bc * 2 + 1] = make_float4(pb.z, pb.z, pb.w, pb.w);
            s_eb[br][bc] = peb;
            if (tid < 16)      s_w [tid]      = pw;
            else if (tid < 32) s_aw[tid - 16] = paw;
            __syncthreads();

            if (c < 15) {
                int k0 = (c + 1) * 16;
                int ga = (k0 + ar) * (NN / 4) + (j0 >> 2) + ac;
                pa0  = AT4 [ga];            pea0 = EAT4[ga];
                pa1  = AT4 [ga + 8 * (NN / 4)];
                pea1 = EAT4[ga + 8 * (NN / 4)];
                int gb = (k0 + br) * (NN / 4) + (i0 >> 2) + bc;
                pb  = BT4 [gb];
                peb = EBT4[gb];
                if (tid < 16)      pw  = g_hw2[k0 + tid];
                else if (tid < 32) paw = g_aw2[k0 + tid - 16];
            }

            #pragma unroll
            for (int kk = 0; kk < 16; kk++) {
                ulonglong2 a2  = *reinterpret_cast<const ulonglong2*>(&s_a [kk][tx]);
                float4     ea  = s_ea[kk][tx];
                ulonglong2 bd0 = *reinterpret_cast<const ulonglong2*>(&s_bd[kk][ty * 2]);
                ulonglong2 bd1 = *reinterpret_cast<const ulonglong2*>(&s_bd[kk][ty * 2 + 1]);
                float4     eb  = s_eb[kk][ty];
                ull w2  = *reinterpret_cast<const ull*>(&s_w [kk]);
                ull aw2 = *reinterpret_cast<const ull*>(&s_aw[kk]);

                ull   ap[2]  = {a2.x, a2.y};
                ull   bp[4]  = {bd0.x, bd0.y, bd1.x, bd1.y};
                float eav[4] = {ea.x, ea.y, ea.z, ea.w};
                float ebv[4] = {eb.x, eb.y, eb.z, eb.w};

                #pragma unroll
                for (int i = 0; i < 4; i++) {
                    #pragma unroll
                    for (int jp = 0; jp < 2; jp++) {
                        ull v2;
                        ADD2(v2, ap[jp], bp[i]);
                        ull av2 = v2 & 0x7FFFFFFF7FFFFFFFull;   // packed |v|
                        FMA2(acc[i][jp], av2, w2, acc[i][jp]);
                        float e0, e1;
                        MULSAT(e0, eav[2 * jp],     ebv[i]);
                        MULSAT(e1, eav[2 * jp + 1], ebv[i]);
                        ull e2;
                        PACK2(e2, e0, e1);
                        FMA2(acc[i][jp], e2, aw2, acc[i][jp]);
                    }
                }
            }
        }

        // epilogue
        float4 Pv = *reinterpret_cast<const float4*>(&g_P[j0 + tx * 4]);
        #pragma unroll
        for (int i = 0; i < 4; i++) {
            int   irow = i0 + ty * 4 + i;
            float base = g_Q[irow] + c0 + 3.0f;
            float a0, a1, a2f, a3;
            UNPACK2(a0,  a1, acc[i][0]);
            UNPACK2(a2f, a3, acc[i][1]);
            float4 o;
            o.x = fminf(fmaxf(a0  + Pv.x + base, 0.f), 6.f) * (1.f / 6.f);
            o.y = fminf(fmaxf(a1  + Pv.y + base, 0.f), 6.f) * (1.f / 6.f);
            o.z = fminf(fmaxf(a2f + Pv.z + base, 0.f), 6.f) * (1.f / 6.f);
            o.w = fminf(fmaxf(a3  + Pv.w + base, 0.f), 6.f) * (1.f / 6.f);
            *reinterpret_cast<float4*>(&out[irow * NN + j0 + tx * 4]) = o;
        }
    }
}

// ---------------------------------------------------------------------------
extern "C" void kernel_launch(void* const* d_in, const int* in_sizes, int n_in,
                              void* d_out, int out_size) {
    const float* x     = (const float*)d_in[0];
    const float* W_enc = (const float*)d_in[1];
    const float* b_enc = (const float*)d_in[2];
    const float* W1    = (const float*)d_in[3];
    const float* b1    = (const float*)d_in[4];
    const float* W2    = (const float*)d_in[5];
    const float* b2    = (const float*)d_in[6];
    float* out = (float*)d_out;

    aux_kernel<<<NN / 8, 256>>>(x, W_enc, b_enc, W1, b1, W2, b2);
    main_kernel<<<592, 128>>>(out);
}

// round 5
// speedup vs baseline: 1.4680x; 1.4680x over previous
#include <cuda_runtime.h>

#define NN  1024
#define RAW 128
#define DD  128
#define HH  256

#define SELU_ALPHA 1.6732632423543772f
#define SELU_SCALE 1.0507009873554805f

typedef unsigned long long ull;

#define UNPACK2(lo, hi, s) asm("mov.b64 {%0, %1}, %2;" : "=f"(lo), "=f"(hi) : "l"(s))

// Scratch (static __device__ arrays; no allocation)
__device__ float  g_AT [HH * NN];   // A^T (incl. b1)            [k][j]
__device__ float  g_EAT[HH * NN];   // exp(A^T)                  [k][j]
__device__ float2 g_BTD[HH * NN];   // {B,B} dup-packed          [k][i]
__device__ float  g_EBT[HH * NN];   // exp(B^T)                  [k][i]
__device__ float  g_P  [NN];        // P[j] = sum_k (sw_k/2) A[k][j]
__device__ float  g_Q  [NN];        // Q[i] = sum_k (sw_k/2) B[k][i]
__device__ float2 g_hw2[HH];        // {sw/2, sw/2}
__device__ float2 g_aw2[HH];        // {asw, asw}
__device__ float  g_c0;             // b2 - sum asw

// ---------------------------------------------------------------------------
// Fused aux: prep (block 0) + z + A/B GEMMs (smem-staged weights) + exp +
// transposed stores + P/Q rank-1 terms.  256 blocks x 256 threads, 4 rows/blk.
// ---------------------------------------------------------------------------
__global__ __launch_bounds__(256) void aux_kernel(
        const float* __restrict__ x,     const float* __restrict__ W_enc,
        const float* __restrict__ b_enc, const float* __restrict__ W1,
        const float* __restrict__ b1,    const float* __restrict__ W2,
        const float* __restrict__ b2) {
    __shared__ float sx [4][RAW];        // 2 KB
    __shared__ float sz [4][DD];         // 2 KB
    __shared__ float swa[16 * 256];      // 16 KB staged weights (top)
    __shared__ float swb[16 * 256];      // 16 KB staged weights (bottom)
    __shared__ float stV[HH * 5];        // 5 KB  [k][row pad 5]
    __shared__ float stE[HH * 5];        // 5 KB
    __shared__ float redR[8][4];

    const int t  = threadIdx.x;          // k in [0,256)
    const int j0 = blockIdx.x * 4;

    // ---- prep (block 0 only) ----
    if (blockIdx.x == 0) {
        float w   = W2[t];
        float sw  = SELU_SCALE * w;
        float asw = SELU_ALPHA * sw;
        g_hw2[t] = make_float2(0.5f * sw, 0.5f * sw);
        g_aw2[t] = make_float2(asw, asw);
        stV[t] = asw;
        __syncthreads();
        #pragma unroll
        for (int s = 128; s > 0; s >>= 1) {
            if (t < s) stV[t] += stV[t + s];
            __syncthreads();
        }
        if (t == 0) g_c0 = b2[0] - stV[0];
        __syncthreads();
    }

    // ---- load x rows (4 x 128 = 512 floats) ----
    #pragma unroll
    for (int s = 0; s < 2; s++) {
        int idx = t + s * 256;
        sx[idx >> 7][idx & 127] = x[(j0 + (idx >> 7)) * RAW + (idx & 127)];
    }
    __syncthreads();

    // ---- z = x @ W_enc + b_enc, staged in chunks of 16 c-rows ----
    {
        const int k  = t & 127;
        const int rh = t >> 7;           // 0/1 -> rows {2rh, 2rh+1}
        float za0 = 0.f, za1 = 0.f;
        for (int c0 = 0; c0 < RAW; c0 += 16) {
            // stage W_enc[c0..c0+16][0..128) = 512 float4
            const float4* src = reinterpret_cast<const float4*>(W_enc + c0 * DD);
            float4* dst = reinterpret_cast<float4*>(swa);
            dst[t]       = src[t];
            dst[t + 256] = src[t + 256];
            __syncthreads();
            #pragma unroll
            for (int cc = 0; cc < 16; cc++) {
                float w = swa[cc * DD + k];
                za0 = fmaf(sx[2 * rh][c0 + cc],     w, za0);
                za1 = fmaf(sx[2 * rh + 1][c0 + cc], w, za1);
            }
            __syncthreads();
        }
        float bb = b_enc[k];
        sz[2 * rh][k]     = za0 + bb;
        sz[2 * rh + 1][k] = za1 + bb;
    }
    __syncthreads();

    // ---- A = z@W1[:d]+b1 ; B = z@W1[d:], staged weights ----
    float accA[4] = {0.f, 0.f, 0.f, 0.f};
    float accB[4] = {0.f, 0.f, 0.f, 0.f};
    for (int c0 = 0; c0 < DD; c0 += 16) {
        const float4* srcA = reinterpret_cast<const float4*>(W1 + c0 * HH);
        const float4* srcB = reinterpret_cast<const float4*>(W1 + (c0 + DD) * HH);
        float4* dstA = reinterpret_cast<float4*>(swa);
        float4* dstB = reinterpret_cast<float4*>(swb);
        #pragma unroll
        for (int s = 0; s < 4; s++) {
            dstA[t + s * 256] = srcA[t + s * 256];
            dstB[t + s * 256] = srcB[t + s * 256];
        }
        __syncthreads();
        #pragma unroll
        for (int cc = 0; cc < 16; cc++) {
            float wa = swa[cc * HH + t];
            float wb = swb[cc * HH + t];
            #pragma unroll
            for (int r = 0; r < 4; r++) {
                float zz = sz[r][c0 + cc];
                accA[r] = fmaf(zz, wa, accA[r]);
                accB[r] = fmaf(zz, wb, accB[r]);
            }
        }
        __syncthreads();
    }

    const float b1k = b1[t];
    const float hw  = 0.5f * SELU_SCALE * W2[t];
    const int wid = t >> 5, lid = t & 31;

    // ---- round A: AT/EAT stores + P ----
    {
        float pv[4];
        #pragma unroll
        for (int r = 0; r < 4; r++) {
            float a = accA[r] + b1k;
            stV[t * 5 + r] = a;
            stE[t * 5 + r] = __expf(fminf(fmaxf(a, -60.f), 60.f));
            pv[r] = hw * a;
        }
        #pragma unroll
        for (int r = 0; r < 4; r++) {
            float v = pv[r];
            #pragma unroll
            for (int s = 16; s > 0; s >>= 1)
                v += __shfl_down_sync(0xffffffffu, v, s);
            if (lid == 0) redR[wid][r] = v;
        }
        __syncthreads();
        #pragma unroll
        for (int p = 0; p < 4; p++) {
            int idx = p * 256 + t;
            int k = idx >> 2, j = idx & 3;
            g_AT [k * NN + j0 + j] = stV[k * 5 + j];
            g_EAT[k * NN + j0 + j] = stE[k * 5 + j];
        }
        if (t < 4) {
            float s = 0.f;
            #pragma unroll
            for (int w2i = 0; w2i < 8; w2i++) s += redR[w2i][t];
            g_P[j0 + t] = s;
        }
        __syncthreads();
    }

    // ---- round B: BTD/EBT stores + Q ----
    {
        float pv[4];
        #pragma unroll
        for (int r = 0; r < 4; r++) {
            float b = accB[r];
            stV[t * 5 + r] = b;
            stE[t * 5 + r] = __expf(fminf(fmaxf(b, -60.f), 60.f));
            pv[r] = hw * b;
        }
        #pragma unroll
        for (int r = 0; r < 4; r++) {
            float v = pv[r];
            #pragma unroll
            for (int s = 16; s > 0; s >>= 1)
                v += __shfl_down_sync(0xffffffffu, v, s);
            if (lid == 0) redR[wid][r] = v;
        }
        __syncthreads();
        #pragma unroll
        for (int p = 0; p < 4; p++) {
            int idx = p * 256 + t;
            int k = idx >> 2, j = idx & 3;
            float b = stV[k * 5 + j];
            g_BTD[k * NN + j0 + j] = make_float2(b, b);
            g_EBT[k * NN + j0 + j] = stE[k * 5 + j];
        }
        if (t < 4) {
            float s = 0.f;
            #pragma unroll
            for (int w2i = 0; w2i < 8; w2i++) s += redR[w2i][t];
            g_Q[j0 + t] = s;
        }
    }
}

// ---------------------------------------------------------------------------
// Main: o[i,j] = hsig( P[j] + Q[i] + c0 + sum_k [ hw_k*|v| + asw_k*sat(e) ] )
//   v = A[k][j]+B[k][i], e = EA[k][j]*EB[k][i] = exp(v), sat(e) = min(e,1).
// 64x64 tiles, 256 threads (4x4 per thread), f32x2 packed core via one fused
// asm block per pair: ADD2 / AND-abs / FMA2 / 2xMULSAT / pack / FMA2.
// ---------------------------------------------------------------------------
__global__ __launch_bounds__(256, 3) void main_kernel(float* __restrict__ out) {
    __shared__ float4 s_a [16][16];     // [k][j4]
    __shared__ float4 s_ea[16][16];
    __shared__ ull    s_bd[16 * 64];    // [k][i] dup pairs {b,b}
    __shared__ float4 s_eb[16][16];     // [k][i4]
    __shared__ float2 s_w2 [16];
    __shared__ float2 s_aw2[16];

    const int tid = threadIdx.x;
    const int tx  = tid & 15;    // j quad
    const int ty  = tid >> 4;    // i quad
    const int j0  = blockIdx.x * 64;
    const int i0  = blockIdx.y * 64;

    const float4* AT4  = reinterpret_cast<const float4*>(g_AT);
    const float4* EAT4 = reinterpret_cast<const float4*>(g_EAT);
    const float4* EBT4 = reinterpret_cast<const float4*>(g_EBT);

    const int ar = tid >> 4, ac = tid & 15;   // tile loader coords
    const ull MASK = 0x7FFFFFFF7FFFFFFFull;

    ull acc[4][2];
    #pragma unroll
    for (int i = 0; i < 4; i++) { acc[i][0] = 0ull; acc[i][1] = 0ull; }

    for (int k0 = 0; k0 < HH; k0 += 16) {
        __syncthreads();
        {
            int ga = (k0 + ar) * (NN / 4) + (j0 >> 2) + ac;
            int gb = (k0 + ar) * (NN / 4) + (i0 >> 2) + ac;
            s_a [ar][ac] = AT4 [ga];
            s_ea[ar][ac] = EAT4[ga];
            s_eb[ar][ac] = EBT4[gb];
            // b dup pairs: 512 x 16B chunks, 2 per thread
            #pragma unroll
            for (int h = 0; h < 2; h++) {
                int ch = tid + h * 256;
                int kr = ch >> 5, c = ch & 31;
                ulonglong2 v = reinterpret_cast<const ulonglong2*>(
                                   &g_BTD[(k0 + kr) * NN + i0])[c];
                reinterpret_cast<ulonglong2*>(&s_bd[kr * 64])[c] = v;
            }
            if (tid < 16)      s_w2 [tid]      = g_hw2[k0 + tid];
            else if (tid < 32) s_aw2[tid - 16] = g_aw2[k0 + tid - 16];
        }
        __syncthreads();

        #pragma unroll
        for (int kk = 0; kk < 16; kk++) {
            ulonglong2 a2  = *reinterpret_cast<const ulonglong2*>(&s_a[kk][tx]);
            float4     ea  = s_ea[kk][tx];
            ulonglong2 bdA = reinterpret_cast<const ulonglong2*>(&s_bd[kk * 64 + ty * 4])[0];
            ulonglong2 bdB = reinterpret_cast<const ulonglong2*>(&s_bd[kk * 64 + ty * 4])[1];
            float4     eb  = s_eb[kk][ty];
            ull w2  = *reinterpret_cast<const ull*>(&s_w2 [kk]);
            ull aw2 = *reinterpret_cast<const ull*>(&s_aw2[kk]);

            ull   ap[2]  = {a2.x, a2.y};
            ull   bp[4]  = {bdA.x, bdA.y, bdB.x, bdB.y};
            float eav[4] = {ea.x, ea.y, ea.z, ea.w};
            float ebv[4] = {eb.x, eb.y, eb.z, eb.w};

            #pragma unroll
            for (int i = 0; i < 4; i++) {
                #pragma unroll
                for (int jp = 0; jp < 2; jp++) {
                    asm("{\n\t"
                        ".reg .b64 v, e;\n\t"
                        ".reg .f32 e0, e1;\n\t"
                        "add.rn.f32x2 v, %1, %2;\n\t"
                        "and.b64 v, v, %3;\n\t"
                        "fma.rn.f32x2 %0, v, %4, %0;\n\t"
                        "mul.rn.sat.f32 e0, %5, %7;\n\t"
                        "mul.rn.sat.f32 e1, %6, %7;\n\t"
                        "mov.b64 e, {e0, e1};\n\t"
                        "fma.rn.f32x2 %0, e, %8, %0;\n\t"
                        "}"
                        : "+l"(acc[i][jp])
                        : "l"(ap[jp]), "l"(bp[i]), "l"(MASK), "l"(w2),
                          "f"(eav[2 * jp]), "f"(eav[2 * jp + 1]),
                          "f"(ebv[i]), "l"(aw2));
                }
            }
        }
    }

    // epilogue: + P[j] + Q[i] + c0, hard_sigmoid
    const float c0 = g_c0;
    float4 Pv = *reinterpret_cast<const float4*>(&g_P[j0 + tx * 4]);
    #pragma unroll
    for (int i = 0; i < 4; i++) {
        int   irow = i0 + ty * 4 + i;
        float base = g_Q[irow] + c0 + 3.0f;
        float a0, a1, a2f, a3;
        UNPACK2(a0,  a1, acc[i][0]);
        UNPACK2(a2f, a3, acc[i][1]);
        float4 o;
        o.x = fminf(fmaxf(a0  + Pv.x + base, 0.f), 6.f) * (1.f / 6.f);
        o.y = fminf(fmaxf(a1  + Pv.y + base, 0.f), 6.f) * (1.f / 6.f);
        o.z = fminf(fmaxf(a2f + Pv.z + base, 0.f), 6.f) * (1.f / 6.f);
        o.w = fminf(fmaxf(a3  + Pv.w + base, 0.f), 6.f) * (1.f / 6.f);
        *reinterpret_cast<float4*>(&out[irow * NN + j0 + tx * 4]) = o;
    }
}

// ---------------------------------------------------------------------------
extern "C" void kernel_launch(void* const* d_in, const int* in_sizes, int n_in,
                              void* d_out, int out_size) {
    const float* x     = (const float*)d_in[0];
    const float* W_enc = (const float*)d_in[1];
    const float* b_enc = (const float*)d_in[2];
    const float* W1    = (const float*)d_in[3];
    const float* b1    = (const float*)d_in[4];
    const float* W2    = (const float*)d_in[5];
    const float* b2    = (const float*)d_in[6];
    float* out = (float*)d_out;

    aux_kernel<<<NN / 4, 256>>>(x, W_enc, b_enc, W1, b1, W2, b2);

    dim3 grid(NN / 64, NN / 64);
    main_kernel<<<grid, 256>>>(out);
}

// round 6
// speedup vs baseline: 1.6349x; 1.1138x over previous
#include <cuda_runtime.h>

#define NN  1024
#define RAW 128
#define DD  128
#define HH  256

#define SELU_ALPHA 1.6732632423543772f
#define SELU_SCALE 1.0507009873554805f

typedef unsigned long long ull;

#define UNPACK2(lo, hi, s) asm("mov.b64 {%0, %1}, %2;" : "=f"(lo), "=f"(hi) : "l"(s))
#define CP16(dst, src) \
    asm volatile("cp.async.cg.shared.global [%0], [%1], 16;" \
                 :: "r"((unsigned)(dst)), "l"(src))
#define CP_COMMIT() asm volatile("cp.async.commit_group;" ::: "memory")
#define CP_WAIT0()  asm volatile("cp.async.wait_group 0;" ::: "memory")

// Scratch (static __device__ arrays; no allocation)
__device__ float  g_AT  [HH * NN];   // A^T (incl. b1)            [k][j]
__device__ float  g_EAT [HH * NN];   // exp(A^T)                  [k][j]
__device__ float2 g_BTD [HH * NN];   // {B,B} dup-packed          [k][i]
__device__ float  g_EBT [HH * NN];   // exp(B^T)                  [k][i]
__device__ float  g_P   [NN];        // P[j] = sum_k (sw_k/2) A[k][j]
__device__ float  g_Q   [NN];        // Q[i] = sum_k (sw_k/2) B[k][i]
__device__ float4 g_hwaw[HH];        // {sw/2, sw/2, asw, asw}
__device__ float  g_c0;              // b2 - sum asw

// ---------------------------------------------------------------------------
// Fused aux: prep (block 0) + z + A/B GEMMs (smem-staged weights) + exp +
// transposed stores + P/Q rank-1 terms.  256 blocks x 256 threads, 4 rows/blk.
// ---------------------------------------------------------------------------
__global__ __launch_bounds__(256) void aux_kernel(
        const float* __restrict__ x,     const float* __restrict__ W_enc,
        const float* __restrict__ b_enc, const float* __restrict__ W1,
        const float* __restrict__ b1,    const float* __restrict__ W2,
        const float* __restrict__ b2) {
    __shared__ float sx [4][RAW];
    __shared__ float sz [4][DD];
    __shared__ float swa[16 * 256];
    __shared__ float swb[16 * 256];
    __shared__ float stV[HH * 5];
    __shared__ float stE[HH * 5];
    __shared__ float redR[8][4];

    const int t  = threadIdx.x;          // k in [0,256)
    const int j0 = blockIdx.x * 4;

    // ---- prep (block 0 only) ----
    if (blockIdx.x == 0) {
        float w   = W2[t];
        float sw  = SELU_SCALE * w;
        float asw = SELU_ALPHA * sw;
        float hw  = 0.5f * sw;
        g_hwaw[t] = make_float4(hw, hw, asw, asw);
        stV[t] = asw;
        __syncthreads();
        #pragma unroll
        for (int s = 128; s > 0; s >>= 1) {
            if (t < s) stV[t] += stV[t + s];
            __syncthreads();
        }
        if (t == 0) g_c0 = b2[0] - stV[0];
        __syncthreads();
    }

    // ---- load x rows (4 x 128 = 512 floats) ----
    #pragma unroll
    for (int s = 0; s < 2; s++) {
        int idx = t + s * 256;
        sx[idx >> 7][idx & 127] = x[(j0 + (idx >> 7)) * RAW + (idx & 127)];
    }
    __syncthreads();

    // ---- z = x @ W_enc + b_enc, staged in chunks of 16 c-rows ----
    {
        const int k  = t & 127;
        const int rh = t >> 7;
        float za0 = 0.f, za1 = 0.f;
        for (int c0 = 0; c0 < RAW; c0 += 16) {
            const float4* src = reinterpret_cast<const float4*>(W_enc + c0 * DD);
            float4* dst = reinterpret_cast<float4*>(swa);
            dst[t]       = src[t];
            dst[t + 256] = src[t + 256];
            __syncthreads();
            #pragma unroll
            for (int cc = 0; cc < 16; cc++) {
                float w = swa[cc * DD + k];
                za0 = fmaf(sx[2 * rh][c0 + cc],     w, za0);
                za1 = fmaf(sx[2 * rh + 1][c0 + cc], w, za1);
            }
            __syncthreads();
        }
        float bb = b_enc[k];
        sz[2 * rh][k]     = za0 + bb;
        sz[2 * rh + 1][k] = za1 + bb;
    }
    __syncthreads();

    // ---- A = z@W1[:d]+b1 ; B = z@W1[d:], staged weights ----
    float accA[4] = {0.f, 0.f, 0.f, 0.f};
    float accB[4] = {0.f, 0.f, 0.f, 0.f};
    for (int c0 = 0; c0 < DD; c0 += 16) {
        const float4* srcA = reinterpret_cast<const float4*>(W1 + c0 * HH);
        const float4* srcB = reinterpret_cast<const float4*>(W1 + (c0 + DD) * HH);
        float4* dstA = reinterpret_cast<float4*>(swa);
        float4* dstB = reinterpret_cast<float4*>(swb);
        #pragma unroll
        for (int s = 0; s < 4; s++) {
            dstA[t + s * 256] = srcA[t + s * 256];
            dstB[t + s * 256] = srcB[t + s * 256];
        }
        __syncthreads();
        #pragma unroll
        for (int cc = 0; cc < 16; cc++) {
            float wa = swa[cc * HH + t];
            float wb = swb[cc * HH + t];
            #pragma unroll
            for (int r = 0; r < 4; r++) {
                float zz = sz[r][c0 + cc];
                accA[r] = fmaf(zz, wa, accA[r]);
                accB[r] = fmaf(zz, wb, accB[r]);
            }
        }
        __syncthreads();
    }

    const float b1k = b1[t];
    const float hw  = 0.5f * SELU_SCALE * W2[t];
    const int wid = t >> 5, lid = t & 31;

    // ---- round A: AT/EAT stores + P ----
    {
        float pv[4];
        #pragma unroll
        for (int r = 0; r < 4; r++) {
            float a = accA[r] + b1k;
            stV[t * 5 + r] = a;
            stE[t * 5 + r] = __expf(fminf(fmaxf(a, -60.f), 60.f));
            pv[r] = hw * a;
        }
        #pragma unroll
        for (int r = 0; r < 4; r++) {
            float v = pv[r];
            #pragma unroll
            for (int s = 16; s > 0; s >>= 1)
                v += __shfl_down_sync(0xffffffffu, v, s);
            if (lid == 0) redR[wid][r] = v;
        }
        __syncthreads();
        #pragma unroll
        for (int p = 0; p < 4; p++) {
            int idx = p * 256 + t;
            int k = idx >> 2, j = idx & 3;
            g_AT [k * NN + j0 + j] = stV[k * 5 + j];
            g_EAT[k * NN + j0 + j] = stE[k * 5 + j];
        }
        if (t < 4) {
            float s = 0.f;
            #pragma unroll
            for (int w2i = 0; w2i < 8; w2i++) s += redR[w2i][t];
            g_P[j0 + t] = s;
        }
        __syncthreads();
    }

    // ---- round B: BTD/EBT stores + Q ----
    {
        float pv[4];
        #pragma unroll
        for (int r = 0; r < 4; r++) {
            float b = accB[r];
            stV[t * 5 + r] = b;
            stE[t * 5 + r] = __expf(fminf(fmaxf(b, -60.f), 60.f));
            pv[r] = hw * b;
        }
        #pragma unroll
        for (int r = 0; r < 4; r++) {
            float v = pv[r];
            #pragma unroll
            for (int s = 16; s > 0; s >>= 1)
                v += __shfl_down_sync(0xffffffffu, v, s);
            if (lid == 0) redR[wid][r] = v;
        }
        __syncthreads();
        #pragma unroll
        for (int p = 0; p < 4; p++) {
            int idx = p * 256 + t;
            int k = idx >> 2, j = idx & 3;
            float b = stV[k * 5 + j];
            g_BTD[k * NN + j0 + j] = make_float2(b, b);
            g_EBT[k * NN + j0 + j] = stE[k * 5 + j];
        }
        if (t < 4) {
            float s = 0.f;
            #pragma unroll
            for (int w2i = 0; w2i < 8; w2i++) s += redR[w2i][t];
            g_Q[j0 + t] = s;
        }
    }
}

// ---------------------------------------------------------------------------
// Main: o[i,j] = hsig( P[j] + Q[i] + c0 + sum_k [ hw_k*|v| + asw_k*sat(e) ] )
//   v = A[k][j]+B[k][i], e = EA[k][j]*EB[k][i] = exp(v), sat(e) = min(e,1).
// 64x64 tiles, 256 threads (4x4/thread). Double-buffered cp.async pipeline,
// one __syncthreads per 16-k chunk. f32x2 packed core.
// ---------------------------------------------------------------------------
__global__ __launch_bounds__(256, 2) void main_kernel(float* __restrict__ out) {
    __shared__ float4 s_a [2][16][16];   // [buf][k][j4]
    __shared__ float4 s_ea[2][16][16];
    __shared__ ull    s_bd[2][16][64];   // [buf][k][i] dup pairs {b,b}
    __shared__ float4 s_eb[2][16][16];
    __shared__ float4 s_wa[2][16];       // {hw,hw,asw,asw}

    const int tid = threadIdx.x;
    const int tx  = tid & 15;    // j quad
    const int ty  = tid >> 4;    // i quad
    const int j0  = blockIdx.x * 64;
    const int i0  = blockIdx.y * 64;

    const float4* AT4  = reinterpret_cast<const float4*>(g_AT);
    const float4* EAT4 = reinterpret_cast<const float4*>(g_EAT);
    const float4* EBT4 = reinterpret_cast<const float4*>(g_EBT);

    const int ar = tid >> 4, ac = tid & 15;       // a/ea/eb loader coords
    const int b0r = tid >> 5,          b0c = tid & 31;        // bd chunk 0
    const int b1r = (tid + 256) >> 5,  b1c = tid & 31;        // bd chunk 1
    const ull MASK = 0x7FFFFFFF7FFFFFFFull;

    // per-thread source offsets (advance by 16 rows per chunk)
    const int gja = ar * (NN / 4) + (j0 >> 2) + ac;
    const int gib = ar * (NN / 4) + (i0 >> 2) + ac;

    ull acc[4][2];
    #pragma unroll
    for (int i = 0; i < 4; i++) { acc[i][0] = 0ull; acc[i][1] = 0ull; }

    // ---- issue chunk 0 loads ----
    {
        CP16(__cvta_generic_to_shared(&s_a [0][ar][ac]), AT4  + gja);
        CP16(__cvta_generic_to_shared(&s_ea[0][ar][ac]), EAT4 + gja);
        CP16(__cvta_generic_to_shared(&s_eb[0][ar][ac]), EBT4 + gib);
        CP16(__cvta_generic_to_shared(&s_bd[0][b0r][b0c * 2]),
             reinterpret_cast<const ulonglong2*>(&g_BTD[b0r * NN + i0]) + b0c);
        CP16(__cvta_generic_to_shared(&s_bd[0][b1r & 15][b1c * 2]),
             reinterpret_cast<const ulonglong2*>(&g_BTD[b1r * NN + i0]) + b1c);
        if (tid < 16)
            CP16(__cvta_generic_to_shared(&s_wa[0][tid]), &g_hwaw[tid]);
        CP_COMMIT();
    }

    int buf = 0;
    for (int c = 0; c < 16; c++) {
        CP_WAIT0();
        __syncthreads();

        if (c < 15) {
            int k0 = (c + 1) * 16;
            int nb = buf ^ 1;
            int oa = k0 * (NN / 4);
            CP16(__cvta_generic_to_shared(&s_a [nb][ar][ac]), AT4  + gja + oa);
            CP16(__cvta_generic_to_shared(&s_ea[nb][ar][ac]), EAT4 + gja + oa);
            CP16(__cvta_generic_to_shared(&s_eb[nb][ar][ac]), EBT4 + gib + oa);
            CP16(__cvta_generic_to_shared(&s_bd[nb][b0r][b0c * 2]),
                 reinterpret_cast<const ulonglong2*>(&g_BTD[(k0 + b0r) * NN + i0]) + b0c);
            CP16(__cvta_generic_to_shared(&s_bd[nb][b1r & 15][b1c * 2]),
                 reinterpret_cast<const ulonglong2*>(&g_BTD[(k0 + (b1r & 15)) * NN + i0]) + b1c);
            if (tid < 16)
                CP16(__cvta_generic_to_shared(&s_wa[nb][tid]), &g_hwaw[k0 + tid]);
            CP_COMMIT();
        }

        #pragma unroll
        for (int kk = 0; kk < 16; kk++) {
            ulonglong2 a2  = *reinterpret_cast<const ulonglong2*>(&s_a[buf][kk][tx]);
            float4     ea  = s_ea[buf][kk][tx];
            ulonglong2 bdA = *reinterpret_cast<const ulonglong2*>(&s_bd[buf][kk][ty * 4]);
            ulonglong2 bdB = *reinterpret_cast<const ulonglong2*>(&s_bd[buf][kk][ty * 4 + 2]);
            float4     eb  = s_eb[buf][kk][ty];
            ulonglong2 wa  = *reinterpret_cast<const ulonglong2*>(&s_wa[buf][kk]);
            ull w2 = wa.x, aw2 = wa.y;

            ull   ap[2]  = {a2.x, a2.y};
            ull   bp[4]  = {bdA.x, bdA.y, bdB.x, bdB.y};
            float eav[4] = {ea.x, ea.y, ea.z, ea.w};
            float ebv[4] = {eb.x, eb.y, eb.z, eb.w};

            #pragma unroll
            for (int i = 0; i < 4; i++) {
                #pragma unroll
                for (int jp = 0; jp < 2; jp++) {
                    asm("{\n\t"
                        ".reg .b64 v, e;\n\t"
                        ".reg .f32 e0, e1;\n\t"
                        "add.rn.f32x2 v, %1, %2;\n\t"
                        "and.b64 v, v, %3;\n\t"
                        "fma.rn.f32x2 %0, v, %4, %0;\n\t"
                        "mul.rn.sat.f32 e0, %5, %7;\n\t"
                        "mul.rn.sat.f32 e1, %6, %7;\n\t"
                        "mov.b64 e, {e0, e1};\n\t"
                        "fma.rn.f32x2 %0, e, %8, %0;\n\t"
                        "}"
                        : "+l"(acc[i][jp])
                        : "l"(ap[jp]), "l"(bp[i]), "l"(MASK), "l"(w2),
                          "f"(eav[2 * jp]), "f"(eav[2 * jp + 1]),
                          "f"(ebv[i]), "l"(aw2));
                }
            }
        }
        buf ^= 1;
    }

    // epilogue: + P[j] + Q[i] + c0, hard_sigmoid
    const float c0 = g_c0;
    float4 Pv = *reinterpret_cast<const float4*>(&g_P[j0 + tx * 4]);
    #pragma unroll
    for (int i = 0; i < 4; i++) {
        int   irow = i0 + ty * 4 + i;
        float base = g_Q[irow] + c0 + 3.0f;
        float a0, a1, a2f, a3;
        UNPACK2(a0,  a1, acc[i][0]);
        UNPACK2(a2f, a3, acc[i][1]);
        float4 o;
        o.x = fminf(fmaxf(a0  + Pv.x + base, 0.f), 6.f) * (1.f / 6.f);
        o.y = fminf(fmaxf(a1  + Pv.y + base, 0.f), 6.f) * (1.f / 6.f);
        o.z = fminf(fmaxf(a2f + Pv.z + base, 0.f), 6.f) * (1.f / 6.f);
        o.w = fminf(fmaxf(a3  + Pv.w + base, 0.f), 6.f) * (1.f / 6.f);
        *reinterpret_cast<float4*>(&out[irow * NN + j0 + tx * 4]) = o;
    }
}

// ---------------------------------------------------------------------------
extern "C" void kernel_launch(void* const* d_in, const int* in_sizes, int n_in,
                              void* d_out, int out_size) {
    const float* x     = (const float*)d_in[0];
    const float* W_enc = (const float*)d_in[1];
    const float* b_enc = (const float*)d_in[2];
    const float* W1    = (const float*)d_in[3];
    const float* b1    = (const float*)d_in[4];
    const float* W2    = (const float*)d_in[5];
    const float* b2    = (const float*)d_in[6];
    float* out = (float*)d_out;

    aux_kernel<<<NN / 4, 256>>>(x, W_enc, b_enc, W1, b1, W2, b2);

    dim3 grid(NN / 64, NN / 64);
    main_kernel<<<grid, 256>>>(out);
}